// round 10
// baseline (speedup 1.0000x reference)
#include <cuda_runtime.h>
#include <cuda_fp16.h>
#include <stdint.h>

// ValueQuantizer: per-32-group 4-bit asymmetric quant + pack + f16 scale/zero + dequant.
// R10 = R9 + paired store grouping: per 2 rows, issue both packed stores back-to-back
// (512B contiguous run) then both vhat stores (1KB contiguous run), halving the
// output-region switch rate in the write stream. All else identical to R9.

#define RPT 4  // rows processed per warp (independent load pipelines)

__device__ __forceinline__ uint32_t f2key(float f) {
    uint32_t b = __float_as_uint(f);
    return b ^ (uint32_t)(((int32_t)b >> 31) | 0x80000000);
}
__device__ __forceinline__ float key2f(uint32_t k) {
    uint32_t b = k ^ (uint32_t)((((int32_t)(~k)) >> 31) | 0x80000000);
    return __uint_as_float(b);
}

struct QOut {
    float i0, i1, i2, i3;  // quant digits as exact-integer floats
    float s, z;            // f16-roundtripped scale / zero (as f32)
    float scale, mn;       // full-precision scale / zero
};

__device__ __forceinline__ QOut quant_core(const float4 x, unsigned mask)
{
    float mnl = fminf(fminf(x.x, x.y), fminf(x.z, x.w));
    float mxl = fmaxf(fmaxf(x.x, x.y), fmaxf(x.z, x.w));
    float mn = key2f(__reduce_min_sync(mask, f2key(mnl)));
    float mx = key2f(__reduce_max_sync(mask, f2key(mxl)));

    float d     = mx - mn;
    float scale = fmaxf(__fmul_rn(d, 1.0f / 15.0f), 1e-8f);

    QOut q;
    q.scale = scale;
    q.mn    = mn;
    q.s = __half2float(__float2half_rn(scale));
    q.z = __half2float(__float2half_rn(mn));

    float r;
    asm("rcp.approx.f32 %0, %1;" : "=f"(r) : "f"(scale));

    // x - mn >= +0 exactly; result lands in [0,15] after rint, no clamp needed
    q.i0 = rintf((x.x - mn) * r);
    q.i1 = rintf((x.y - mn) * r);
    q.i2 = rintf((x.z - mn) * r);
    q.i3 = rintf((x.w - mn) * r);
    return q;
}

// Primary path: outputs concatenated as float32: [packed | scales | zeros | v_hat]
__global__ __launch_bounds__(256, 6)
void vq_float_concat(const float4* __restrict__ v4,
                     float* __restrict__ out,
                     int rows)
{
    int tid  = blockIdx.x * blockDim.x + threadIdx.x;
    int lane = tid & 31;
    int warp = tid >> 5;
    int row0 = warp * RPT;
    if (row0 >= rows) return;

    const unsigned mask = 0xFFu << (lane & 24);

    // front-batched independent loads: 4 outstanding LDG.128 per thread, evict-first
    const float4* base = v4 + (size_t)row0 * 32 + lane;
    float4 x[RPT];
#pragma unroll
    for (int r = 0; r < RPT; r++) x[r] = __ldcs(base + (size_t)r * 32);

    float* out_packed = out;                              // rows*64
    float* out_scales = out + (size_t)rows * 64;          // rows*4
    float* out_zeros  = out + (size_t)rows * 68;          // rows*4
    float* out_vhat   = out + (size_t)rows * 72;          // rows*128

    float sA[RPT], zA[RPT];

    // process in pairs: group packed stores then vhat stores per pair
#pragma unroll
    for (int p = 0; p < RPT / 2; p++) {
        QOut qa = quant_core(x[2 * p + 0], mask);
        QOut qb = quant_core(x[2 * p + 1], mask);
        sA[2 * p + 0] = qa.s;  zA[2 * p + 0] = qa.z;
        sA[2 * p + 1] = qb.s;  zA[2 * p + 1] = qb.z;

        size_t gia = (size_t)(row0 + 2 * p + 0) * 32 + lane;
        size_t gib = (size_t)(row0 + 2 * p + 1) * 32 + lane;

        // both packed bursts back-to-back: 512B contiguous run per warp
        __stcs(reinterpret_cast<float2*>(out_packed) + gia,
               make_float2(fmaf(qa.i1, 16.0f, qa.i0), fmaf(qa.i3, 16.0f, qa.i2)));
        __stcs(reinterpret_cast<float2*>(out_packed) + gib,
               make_float2(fmaf(qb.i1, 16.0f, qb.i0), fmaf(qb.i3, 16.0f, qb.i2)));

        // both vhat bursts back-to-back: 1KB contiguous run per warp
        float4 va, vb;
        va.x = fmaf(qa.i0, qa.s, qa.z);
        va.y = fmaf(qa.i1, qa.s, qa.z);
        va.z = fmaf(qa.i2, qa.s, qa.z);
        va.w = fmaf(qa.i3, qa.s, qa.z);
        vb.x = fmaf(qb.i0, qb.s, qb.z);
        vb.y = fmaf(qb.i1, qb.s, qb.z);
        vb.z = fmaf(qb.i2, qb.s, qb.z);
        vb.w = fmaf(qb.i3, qb.s, qb.z);
        __stcs(reinterpret_cast<float4*>(out_vhat) + gia, va);
        __stcs(reinterpret_cast<float4*>(out_vhat) + gib, vb);
    }

    // scale/zero stores, gathered: lanes 0-15 write the warp's 16 consecutive
    // scales, lanes 16-31 the 16 consecutive zeros (two 64B contiguous bursts).
    {
        int li = lane & 15;          // flat index within the warp's 16 groups
        int src = (li & 3) * 8;      // lane holding group g's value (g = li&3)
        float s0 = __shfl_sync(0xffffffffu, sA[0], src);
        float s1 = __shfl_sync(0xffffffffu, sA[1], src);
        float s2 = __shfl_sync(0xffffffffu, sA[2], src);
        float s3 = __shfl_sync(0xffffffffu, sA[3], src);
        float z0 = __shfl_sync(0xffffffffu, zA[0], src);
        float z1 = __shfl_sync(0xffffffffu, zA[1], src);
        float z2 = __shfl_sync(0xffffffffu, zA[2], src);
        float z3 = __shfl_sync(0xffffffffu, zA[3], src);
        int r = li >> 2;
        float sv = (r == 0) ? s0 : (r == 1) ? s1 : (r == 2) ? s2 : s3;
        float zv = (r == 0) ? z0 : (r == 1) ? z1 : (r == 2) ? z2 : z3;

        size_t sbase = (size_t)row0 * 4;  // 16 consecutive floats per warp
        if (lane < 16) __stcs(out_scales + sbase + li, sv);
        else           __stcs(out_zeros  + sbase + li, zv);
    }
}

// Fallback A: output is only v_hat (float32)
__global__ __launch_bounds__(256, 6)
void vq_vhat_only(const float4* __restrict__ v4,
                  float* __restrict__ out,
                  int rows)
{
    int tid  = blockIdx.x * blockDim.x + threadIdx.x;
    int lane = tid & 31;
    int warp = tid >> 5;
    int row0 = warp * RPT;
    if (row0 >= rows) return;
    const unsigned mask = 0xFFu << (lane & 24);

    const float4* base = v4 + (size_t)row0 * 32 + lane;
    float4 x[RPT];
#pragma unroll
    for (int r = 0; r < RPT; r++) x[r] = __ldcs(base + (size_t)r * 32);

#pragma unroll
    for (int r = 0; r < RPT; r++) {
        QOut q = quant_core(x[r], mask);
        size_t gi = (size_t)(row0 + r) * 32 + lane;
        float4 vh;
        vh.x = fmaf(q.i0, q.s, q.z);
        vh.y = fmaf(q.i1, q.s, q.z);
        vh.z = fmaf(q.i2, q.s, q.z);
        vh.w = fmaf(q.i3, q.s, q.z);
        __stcs(reinterpret_cast<float4*>(out) + gi, vh);
    }
}

// Fallback B: native byte concatenation [u8 packed | f16 scales | f16 zeros | f32 v_hat]
__global__ __launch_bounds__(256, 6)
void vq_byte_concat(const float4* __restrict__ v4,
                    uint8_t* __restrict__ out,
                    int rows)
{
    int tid  = blockIdx.x * blockDim.x + threadIdx.x;
    int lane = tid & 31;
    int warp = tid >> 5;
    int row0 = warp * RPT;
    if (row0 >= rows) return;
    const unsigned mask = 0xFFu << (lane & 24);

    const float4* base = v4 + (size_t)row0 * 32 + lane;
    float4 x[RPT];
#pragma unroll
    for (int r = 0; r < RPT; r++) x[r] = __ldcs(base + (size_t)r * 32);

    const size_t PACKED_B = (size_t)rows * 64;      // u8
    const size_t SC_B     = (size_t)rows * 8;       // f16
    uint8_t* out_packed = out;
    __half*  out_scales = reinterpret_cast<__half*>(out + PACKED_B);
    __half*  out_zeros  = reinterpret_cast<__half*>(out + PACKED_B + SC_B);
    float*   out_vhat   = reinterpret_cast<float*>(out + PACKED_B + 2 * SC_B);

#pragma unroll
    for (int r = 0; r < RPT; r++) {
        QOut q = quant_core(x[r], mask);
        size_t gi = (size_t)(row0 + r) * 32 + lane;

        uchar2 pb;
        pb.x = (uint8_t)(unsigned)fmaf(q.i1, 16.0f, q.i0);
        pb.y = (uint8_t)(unsigned)fmaf(q.i3, 16.0f, q.i2);
        reinterpret_cast<uchar2*>(out_packed)[gi] = pb;

        if ((lane & 7) == 0) {
            out_scales[gi >> 3] = __float2half_rn(q.scale);
            out_zeros [gi >> 3] = __float2half_rn(q.mn);
        }

        float4 vh;
        vh.x = fmaf(q.i0, q.s, q.z);
        vh.y = fmaf(q.i1, q.s, q.z);
        vh.z = fmaf(q.i2, q.s, q.z);
        vh.w = fmaf(q.i3, q.s, q.z);
        __stcs(reinterpret_cast<float4*>(out_vhat) + gi, vh);
    }
}

extern "C" void kernel_launch(void* const* d_in, const int* in_sizes, int n_in,
                              void* d_out, int out_size)
{
    const float4* v4 = (const float4*)d_in[0];
    const int n    = in_sizes[0];        // total input floats
    const int rows = n / 128;

    // one warp per RPT rows
    const long long warps   = (rows + RPT - 1) / RPT;
    const long long threads = warps * 32;
    const int block = 256;
    const int grid  = (int)((threads + block - 1) / block);

    if (out_size == rows * 200) {
        vq_float_concat<<<grid, block>>>(v4, (float*)d_out, rows);
    } else if (out_size == rows * 128) {
        vq_vhat_only<<<grid, block>>>(v4, (float*)d_out, rows);
    } else {
        vq_byte_concat<<<grid, block>>>(v4, (uint8_t*)d_out, rows);
    }
}

// round 11
// speedup vs baseline: 1.0003x; 1.0003x over previous
#include <cuda_runtime.h>
#include <cuda_fp16.h>
#include <stdint.h>

// ValueQuantizer: per-32-group 4-bit asymmetric quant + pack + f16 scale/zero + dequant.
// R11 (TERMINAL) = R9/R7: best measured config. Kernel ~99us = 6.8 TB/s aggregate on a
// 62:38 write:read mixed stream = mixed-stream HBM ceiling on GB300. Levers exhausted:
// MLP(1/4/8), occ(44-84%), cache policy, store grouping, persistent scheduling.
// Config: RPT=4 front-batched LDG.128, lb(256,6), ldcs/stcs, shuffle-gathered
// contiguous 64B burst stores for scales/zeros.

#define RPT 4  // rows processed per warp (independent load pipelines)

__device__ __forceinline__ uint32_t f2key(float f) {
    uint32_t b = __float_as_uint(f);
    return b ^ (uint32_t)(((int32_t)b >> 31) | 0x80000000);
}
__device__ __forceinline__ float key2f(uint32_t k) {
    uint32_t b = k ^ (uint32_t)((((int32_t)(~k)) >> 31) | 0x80000000);
    return __uint_as_float(b);
}

struct QOut {
    float i0, i1, i2, i3;  // quant digits as exact-integer floats
    float s, z;            // f16-roundtripped scale / zero (as f32)
    float scale, mn;       // full-precision scale / zero
};

__device__ __forceinline__ QOut quant_core(const float4 x, unsigned mask)
{
    float mnl = fminf(fminf(x.x, x.y), fminf(x.z, x.w));
    float mxl = fmaxf(fmaxf(x.x, x.y), fmaxf(x.z, x.w));
    float mn = key2f(__reduce_min_sync(mask, f2key(mnl)));
    float mx = key2f(__reduce_max_sync(mask, f2key(mxl)));

    float d     = mx - mn;
    float scale = fmaxf(__fmul_rn(d, 1.0f / 15.0f), 1e-8f);

    QOut q;
    q.scale = scale;
    q.mn    = mn;
    q.s = __half2float(__float2half_rn(scale));
    q.z = __half2float(__float2half_rn(mn));

    float r;
    asm("rcp.approx.f32 %0, %1;" : "=f"(r) : "f"(scale));

    // x - mn >= +0 exactly; result lands in [0,15] after rint, no clamp needed
    q.i0 = rintf((x.x - mn) * r);
    q.i1 = rintf((x.y - mn) * r);
    q.i2 = rintf((x.z - mn) * r);
    q.i3 = rintf((x.w - mn) * r);
    return q;
}

// Primary path: outputs concatenated as float32: [packed | scales | zeros | v_hat]
__global__ __launch_bounds__(256, 6)
void vq_float_concat(const float4* __restrict__ v4,
                     float* __restrict__ out,
                     int rows)
{
    int tid  = blockIdx.x * blockDim.x + threadIdx.x;
    int lane = tid & 31;
    int warp = tid >> 5;
    int row0 = warp * RPT;
    if (row0 >= rows) return;

    const unsigned mask = 0xFFu << (lane & 24);

    // front-batched independent loads: 4 outstanding LDG.128 per thread, evict-first
    const float4* base = v4 + (size_t)row0 * 32 + lane;
    float4 x[RPT];
#pragma unroll
    for (int r = 0; r < RPT; r++) x[r] = __ldcs(base + (size_t)r * 32);

    float* out_packed = out;                              // rows*64
    float* out_scales = out + (size_t)rows * 64;          // rows*4
    float* out_zeros  = out + (size_t)rows * 68;          // rows*4
    float* out_vhat   = out + (size_t)rows * 72;          // rows*128

    float sA[RPT], zA[RPT];

#pragma unroll
    for (int r = 0; r < RPT; r++) {
        QOut q = quant_core(x[r], mask);
        sA[r] = q.s;
        zA[r] = q.z;
        size_t gi = (size_t)(row0 + r) * 32 + lane;

        // packed digits as floats: lo + hi*16 (exact small ints)
        __stcs(reinterpret_cast<float2*>(out_packed) + gi,
               make_float2(fmaf(q.i1, 16.0f, q.i0), fmaf(q.i3, 16.0f, q.i2)));

        float4 vh;
        vh.x = fmaf(q.i0, q.s, q.z);
        vh.y = fmaf(q.i1, q.s, q.z);
        vh.z = fmaf(q.i2, q.s, q.z);
        vh.w = fmaf(q.i3, q.s, q.z);
        __stcs(reinterpret_cast<float4*>(out_vhat) + gi, vh);
    }

    // scale/zero stores, gathered: lanes 0-15 write the warp's 16 consecutive
    // scales, lanes 16-31 the 16 consecutive zeros (two 64B contiguous bursts).
    {
        int li = lane & 15;          // flat index within the warp's 16 groups
        int src = (li & 3) * 8;      // lane holding group g's value (g = li&3)
        float s0 = __shfl_sync(0xffffffffu, sA[0], src);
        float s1 = __shfl_sync(0xffffffffu, sA[1], src);
        float s2 = __shfl_sync(0xffffffffu, sA[2], src);
        float s3 = __shfl_sync(0xffffffffu, sA[3], src);
        float z0 = __shfl_sync(0xffffffffu, zA[0], src);
        float z1 = __shfl_sync(0xffffffffu, zA[1], src);
        float z2 = __shfl_sync(0xffffffffu, zA[2], src);
        float z3 = __shfl_sync(0xffffffffu, zA[3], src);
        int r = li >> 2;
        float sv = (r == 0) ? s0 : (r == 1) ? s1 : (r == 2) ? s2 : s3;
        float zv = (r == 0) ? z0 : (r == 1) ? z1 : (r == 2) ? z2 : z3;

        size_t sbase = (size_t)row0 * 4;  // 16 consecutive floats per warp
        if (lane < 16) __stcs(out_scales + sbase + li, sv);
        else           __stcs(out_zeros  + sbase + li, zv);
    }
}

// Fallback A: output is only v_hat (float32)
__global__ __launch_bounds__(256, 6)
void vq_vhat_only(const float4* __restrict__ v4,
                  float* __restrict__ out,
                  int rows)
{
    int tid  = blockIdx.x * blockDim.x + threadIdx.x;
    int lane = tid & 31;
    int warp = tid >> 5;
    int row0 = warp * RPT;
    if (row0 >= rows) return;
    const unsigned mask = 0xFFu << (lane & 24);

    const float4* base = v4 + (size_t)row0 * 32 + lane;
    float4 x[RPT];
#pragma unroll
    for (int r = 0; r < RPT; r++) x[r] = __ldcs(base + (size_t)r * 32);

#pragma unroll
    for (int r = 0; r < RPT; r++) {
        QOut q = quant_core(x[r], mask);
        size_t gi = (size_t)(row0 + r) * 32 + lane;
        float4 vh;
        vh.x = fmaf(q.i0, q.s, q.z);
        vh.y = fmaf(q.i1, q.s, q.z);
        vh.z = fmaf(q.i2, q.s, q.z);
        vh.w = fmaf(q.i3, q.s, q.z);
        __stcs(reinterpret_cast<float4*>(out) + gi, vh);
    }
}

// Fallback B: native byte concatenation [u8 packed | f16 scales | f16 zeros | f32 v_hat]
__global__ __launch_bounds__(256, 6)
void vq_byte_concat(const float4* __restrict__ v4,
                    uint8_t* __restrict__ out,
                    int rows)
{
    int tid  = blockIdx.x * blockDim.x + threadIdx.x;
    int lane = tid & 31;
    int warp = tid >> 5;
    int row0 = warp * RPT;
    if (row0 >= rows) return;
    const unsigned mask = 0xFFu << (lane & 24);

    const float4* base = v4 + (size_t)row0 * 32 + lane;
    float4 x[RPT];
#pragma unroll
    for (int r = 0; r < RPT; r++) x[r] = __ldcs(base + (size_t)r * 32);

    const size_t PACKED_B = (size_t)rows * 64;      // u8
    const size_t SC_B     = (size_t)rows * 8;       // f16
    uint8_t* out_packed = out;
    __half*  out_scales = reinterpret_cast<__half*>(out + PACKED_B);
    __half*  out_zeros  = reinterpret_cast<__half*>(out + PACKED_B + SC_B);
    float*   out_vhat   = reinterpret_cast<float*>(out + PACKED_B + 2 * SC_B);

#pragma unroll
    for (int r = 0; r < RPT; r++) {
        QOut q = quant_core(x[r], mask);
        size_t gi = (size_t)(row0 + r) * 32 + lane;

        uchar2 pb;
        pb.x = (uint8_t)(unsigned)fmaf(q.i1, 16.0f, q.i0);
        pb.y = (uint8_t)(unsigned)fmaf(q.i3, 16.0f, q.i2);
        reinterpret_cast<uchar2*>(out_packed)[gi] = pb;

        if ((lane & 7) == 0) {
            out_scales[gi >> 3] = __float2half_rn(q.scale);
            out_zeros [gi >> 3] = __float2half_rn(q.mn);
        }

        float4 vh;
        vh.x = fmaf(q.i0, q.s, q.z);
        vh.y = fmaf(q.i1, q.s, q.z);
        vh.z = fmaf(q.i2, q.s, q.z);
        vh.w = fmaf(q.i3, q.s, q.z);
        __stcs(reinterpret_cast<float4*>(out_vhat) + gi, vh);
    }
}

extern "C" void kernel_launch(void* const* d_in, const int* in_sizes, int n_in,
                              void* d_out, int out_size)
{
    const float4* v4 = (const float4*)d_in[0];
    const int n    = in_sizes[0];        // total input floats
    const int rows = n / 128;

    // one warp per RPT rows
    const long long warps   = (rows + RPT - 1) / RPT;
    const long long threads = warps * 32;
    const int block = 256;
    const int grid  = (int)((threads + block - 1) / block);

    if (out_size == rows * 200) {
        vq_float_concat<<<grid, block>>>(v4, (float*)d_out, rows);
    } else if (out_size == rows * 128) {
        vq_vhat_only<<<grid, block>>>(v4, (float*)d_out, rows);
    } else {
        vq_byte_concat<<<grid, block>>>(v4, (uint8_t*)d_out, rows);
    }
}

// round 12
// speedup vs baseline: 1.0046x; 1.0043x over previous
#include <cuda_runtime.h>
#include <cuda_fp16.h>
#include <stdint.h>

// ValueQuantizer: per-32-group 4-bit asymmetric quant + pack + f16 scale/zero + dequant.
// TERMINAL (R7/R9/R11 config, 3x validated): kernel ~99.5us = 6.75 TB/s aggregate on a
// 62:38 write:read mixed stream (~84% of HBM3e spec) — the traffic floor for this
// problem's fixed 672MB I/O contract. Levers exhausted: MLP(1/4/8), occ(44-84%),
// cache policy, store grouping (scattered/burst/paired), persistent scheduling.
// Config: RPT=4 front-batched LDG.128, lb(256,6) (40 regs), ldcs/stcs streaming,
// shuffle-gathered contiguous 64B burst stores for scales/zeros.

#define RPT 4  // rows processed per warp (independent load pipelines)

__device__ __forceinline__ uint32_t f2key(float f) {
    uint32_t b = __float_as_uint(f);
    return b ^ (uint32_t)(((int32_t)b >> 31) | 0x80000000);
}
__device__ __forceinline__ float key2f(uint32_t k) {
    uint32_t b = k ^ (uint32_t)((((int32_t)(~k)) >> 31) | 0x80000000);
    return __uint_as_float(b);
}

struct QOut {
    float i0, i1, i2, i3;  // quant digits as exact-integer floats
    float s, z;            // f16-roundtripped scale / zero (as f32)
    float scale, mn;       // full-precision scale / zero
};

__device__ __forceinline__ QOut quant_core(const float4 x, unsigned mask)
{
    float mnl = fminf(fminf(x.x, x.y), fminf(x.z, x.w));
    float mxl = fmaxf(fmaxf(x.x, x.y), fmaxf(x.z, x.w));
    float mn = key2f(__reduce_min_sync(mask, f2key(mnl)));
    float mx = key2f(__reduce_max_sync(mask, f2key(mxl)));

    float d     = mx - mn;
    float scale = fmaxf(__fmul_rn(d, 1.0f / 15.0f), 1e-8f);

    QOut q;
    q.scale = scale;
    q.mn    = mn;
    q.s = __half2float(__float2half_rn(scale));
    q.z = __half2float(__float2half_rn(mn));

    float r;
    asm("rcp.approx.f32 %0, %1;" : "=f"(r) : "f"(scale));

    // x - mn >= +0 exactly; result lands in [0,15] after rint, no clamp needed
    q.i0 = rintf((x.x - mn) * r);
    q.i1 = rintf((x.y - mn) * r);
    q.i2 = rintf((x.z - mn) * r);
    q.i3 = rintf((x.w - mn) * r);
    return q;
}

// Primary path: outputs concatenated as float32: [packed | scales | zeros | v_hat]
__global__ __launch_bounds__(256, 6)
void vq_float_concat(const float4* __restrict__ v4,
                     float* __restrict__ out,
                     int rows)
{
    int tid  = blockIdx.x * blockDim.x + threadIdx.x;
    int lane = tid & 31;
    int warp = tid >> 5;
    int row0 = warp * RPT;
    if (row0 >= rows) return;

    const unsigned mask = 0xFFu << (lane & 24);

    // front-batched independent loads: 4 outstanding LDG.128 per thread, evict-first
    const float4* base = v4 + (size_t)row0 * 32 + lane;
    float4 x[RPT];
#pragma unroll
    for (int r = 0; r < RPT; r++) x[r] = __ldcs(base + (size_t)r * 32);

    float* out_packed = out;                              // rows*64
    float* out_scales = out + (size_t)rows * 64;          // rows*4
    float* out_zeros  = out + (size_t)rows * 68;          // rows*4
    float* out_vhat   = out + (size_t)rows * 72;          // rows*128

    float sA[RPT], zA[RPT];

#pragma unroll
    for (int r = 0; r < RPT; r++) {
        QOut q = quant_core(x[r], mask);
        sA[r] = q.s;
        zA[r] = q.z;
        size_t gi = (size_t)(row0 + r) * 32 + lane;

        // packed digits as floats: lo + hi*16 (exact small ints)
        __stcs(reinterpret_cast<float2*>(out_packed) + gi,
               make_float2(fmaf(q.i1, 16.0f, q.i0), fmaf(q.i3, 16.0f, q.i2)));

        float4 vh;
        vh.x = fmaf(q.i0, q.s, q.z);
        vh.y = fmaf(q.i1, q.s, q.z);
        vh.z = fmaf(q.i2, q.s, q.z);
        vh.w = fmaf(q.i3, q.s, q.z);
        __stcs(reinterpret_cast<float4*>(out_vhat) + gi, vh);
    }

    // scale/zero stores, gathered: lanes 0-15 write the warp's 16 consecutive
    // scales, lanes 16-31 the 16 consecutive zeros (two 64B contiguous bursts).
    {
        int li = lane & 15;          // flat index within the warp's 16 groups
        int src = (li & 3) * 8;      // lane holding group g's value (g = li&3)
        float s0 = __shfl_sync(0xffffffffu, sA[0], src);
        float s1 = __shfl_sync(0xffffffffu, sA[1], src);
        float s2 = __shfl_sync(0xffffffffu, sA[2], src);
        float s3 = __shfl_sync(0xffffffffu, sA[3], src);
        float z0 = __shfl_sync(0xffffffffu, zA[0], src);
        float z1 = __shfl_sync(0xffffffffu, zA[1], src);
        float z2 = __shfl_sync(0xffffffffu, zA[2], src);
        float z3 = __shfl_sync(0xffffffffu, zA[3], src);
        int r = li >> 2;
        float sv = (r == 0) ? s0 : (r == 1) ? s1 : (r == 2) ? s2 : s3;
        float zv = (r == 0) ? z0 : (r == 1) ? z1 : (r == 2) ? z2 : z3;

        size_t sbase = (size_t)row0 * 4;  // 16 consecutive floats per warp
        if (lane < 16) __stcs(out_scales + sbase + li, sv);
        else           __stcs(out_zeros  + sbase + li, zv);
    }
}

// Fallback A: output is only v_hat (float32)
__global__ __launch_bounds__(256, 6)
void vq_vhat_only(const float4* __restrict__ v4,
                  float* __restrict__ out,
                  int rows)
{
    int tid  = blockIdx.x * blockDim.x + threadIdx.x;
    int lane = tid & 31;
    int warp = tid >> 5;
    int row0 = warp * RPT;
    if (row0 >= rows) return;
    const unsigned mask = 0xFFu << (lane & 24);

    const float4* base = v4 + (size_t)row0 * 32 + lane;
    float4 x[RPT];
#pragma unroll
    for (int r = 0; r < RPT; r++) x[r] = __ldcs(base + (size_t)r * 32);

#pragma unroll
    for (int r = 0; r < RPT; r++) {
        QOut q = quant_core(x[r], mask);
        size_t gi = (size_t)(row0 + r) * 32 + lane;
        float4 vh;
        vh.x = fmaf(q.i0, q.s, q.z);
        vh.y = fmaf(q.i1, q.s, q.z);
        vh.z = fmaf(q.i2, q.s, q.z);
        vh.w = fmaf(q.i3, q.s, q.z);
        __stcs(reinterpret_cast<float4*>(out) + gi, vh);
    }
}

// Fallback B: native byte concatenation [u8 packed | f16 scales | f16 zeros | f32 v_hat]
__global__ __launch_bounds__(256, 6)
void vq_byte_concat(const float4* __restrict__ v4,
                    uint8_t* __restrict__ out,
                    int rows)
{
    int tid  = blockIdx.x * blockDim.x + threadIdx.x;
    int lane = tid & 31;
    int warp = tid >> 5;
    int row0 = warp * RPT;
    if (row0 >= rows) return;
    const unsigned mask = 0xFFu << (lane & 24);

    const float4* base = v4 + (size_t)row0 * 32 + lane;
    float4 x[RPT];
#pragma unroll
    for (int r = 0; r < RPT; r++) x[r] = __ldcs(base + (size_t)r * 32);

    const size_t PACKED_B = (size_t)rows * 64;      // u8
    const size_t SC_B     = (size_t)rows * 8;       // f16
    uint8_t* out_packed = out;
    __half*  out_scales = reinterpret_cast<__half*>(out + PACKED_B);
    __half*  out_zeros  = reinterpret_cast<__half*>(out + PACKED_B + SC_B);
    float*   out_vhat   = reinterpret_cast<float*>(out + PACKED_B + 2 * SC_B);

#pragma unroll
    for (int r = 0; r < RPT; r++) {
        QOut q = quant_core(x[r], mask);
        size_t gi = (size_t)(row0 + r) * 32 + lane;

        uchar2 pb;
        pb.x = (uint8_t)(unsigned)fmaf(q.i1, 16.0f, q.i0);
        pb.y = (uint8_t)(unsigned)fmaf(q.i3, 16.0f, q.i2);
        reinterpret_cast<uchar2*>(out_packed)[gi] = pb;

        if ((lane & 7) == 0) {
            out_scales[gi >> 3] = __float2half_rn(q.scale);
            out_zeros [gi >> 3] = __float2half_rn(q.mn);
        }

        float4 vh;
        vh.x = fmaf(q.i0, q.s, q.z);
        vh.y = fmaf(q.i1, q.s, q.z);
        vh.z = fmaf(q.i2, q.s, q.z);
        vh.w = fmaf(q.i3, q.s, q.z);
        __stcs(reinterpret_cast<float4*>(out_vhat) + gi, vh);
    }
}

extern "C" void kernel_launch(void* const* d_in, const int* in_sizes, int n_in,
                              void* d_out, int out_size)
{
    const float4* v4 = (const float4*)d_in[0];
    const int n    = in_sizes[0];        // total input floats
    const int rows = n / 128;

    // one warp per RPT rows
    const long long warps   = (rows + RPT - 1) / RPT;
    const long long threads = warps * 32;
    const int block = 256;
    const int grid  = (int)((threads + block - 1) / block);

    if (out_size == rows * 200) {
        vq_float_concat<<<grid, block>>>(v4, (float*)d_out, rows);
    } else if (out_size == rows * 128) {
        vq_vhat_only<<<grid, block>>>(v4, (float*)d_out, rows);
    } else {
        vq_byte_concat<<<grid, block>>>(v4, (uint8_t*)d_out, rows);
    }
}